// round 1
// baseline (speedup 1.0000x reference)
#include <cuda_runtime.h>
#include <math.h>

#define NN 50000
#define EE 800000
#define FDIM 256   /* HEADS*HID */

// ---------------- scratch (device globals: allowed) ----------------
__device__ float g_ft[(size_t)NN * FDIM];   // per-layer transformed features
__device__ float g_x [(size_t)NN * FDIM];   // layer activations (ping buffer)
__device__ float g_res[(size_t)NN * FDIM];  // layer-1 residual (h @ Wr1)
__device__ float g_el[NN * 4];
__device__ float g_er[NN * 4];
__device__ float g_hf[NN * 64];
__device__ int   g_deg[NN + 1];
__device__ int   g_off[NN + 1];
__device__ int   g_pos[NN];
__device__ int   g_esrc[EE];

__device__ __forceinline__ float lrelu(float x) { return x > 0.f ? x : 0.2f * x; }

// ---------------- CSR build ----------------
__global__ void zero_int_kernel(int* __restrict__ p, int n) {
    int i = blockIdx.x * blockDim.x + threadIdx.x;
    if (i < n) p[i] = 0;
}

__global__ void hist_kernel(const int* __restrict__ dst, int* __restrict__ deg, int e) {
    int i = blockIdx.x * blockDim.x + threadIdx.x;
    if (i < e) atomicAdd(&deg[dst[i]], 1);
}

// single-block exclusive scan over N (~50k) elements
__global__ void scan_kernel(const int* __restrict__ deg, int* __restrict__ off,
                            int* __restrict__ pos, int n) {
    __shared__ int sh[1024];
    int running = 0;
    for (int base = 0; base < n; base += 1024) {
        int i = base + threadIdx.x;
        int v = (i < n) ? deg[i] : 0;
        sh[threadIdx.x] = v;
        __syncthreads();
        for (int o = 1; o < 1024; o <<= 1) {
            int t = (threadIdx.x >= o) ? sh[threadIdx.x - o] : 0;
            __syncthreads();
            sh[threadIdx.x] += t;
            __syncthreads();
        }
        int excl = sh[threadIdx.x] - v;
        if (i < n) { off[i] = running + excl; pos[i] = running + excl; }
        running += sh[1023];
        __syncthreads();
    }
    if (threadIdx.x == 0) off[n] = running;
}

__global__ void scatter_kernel(const int* __restrict__ src, const int* __restrict__ dst,
                               int* __restrict__ pos, int* __restrict__ esrc, int e) {
    int i = blockIdx.x * blockDim.x + threadIdx.x;
    if (i < e) {
        int p = atomicAdd(&pos[dst[i]], 1);
        esrc[p] = src[i];
    }
}

// ---------------- fused GEMM + attention logits ----------------
// One warp per node row. ft = X @ W ; el/er = head-wise <ft, al/ar>.
// RES: additionally res = X @ Wr (layer 1 residual projection).
template <int FIN, bool RES>
__global__ void __launch_bounds__(256) gemm_kernel(
    const float* __restrict__ X, const float* __restrict__ W,
    const float* __restrict__ Wr,
    const float* __restrict__ al, const float* __restrict__ ar,
    float* __restrict__ ft, float* __restrict__ resout,
    float* __restrict__ el, float* __restrict__ er, int n)
{
    __shared__ float sx[8][FIN];
    const int warp = threadIdx.x >> 5;
    const int lane = threadIdx.x & 31;
    const int row  = blockIdx.x * 8 + warp;
    if (row >= n) return;

    const float* xr = X + (size_t)row * FIN;
    #pragma unroll
    for (int k = lane; k < FIN; k += 32) sx[warp][k] = xr[k];
    __syncwarp();

    float acc[8], accr[8];
    #pragma unroll
    for (int j = 0; j < 8; j++) { acc[j] = 0.f; accr[j] = 0.f; }

    const float4* __restrict__ W4  = (const float4*)W;
    const float4* __restrict__ Wr4 = (const float4*)Wr;
    const int c4 = lane * 2;   // this lane owns output cols [lane*8, lane*8+8)

    #pragma unroll 4
    for (int k = 0; k < FIN; k++) {
        float xk = sx[warp][k];
        float4 w0 = W4[(size_t)k * 64 + c4];
        float4 w1 = W4[(size_t)k * 64 + c4 + 1];
        acc[0] = fmaf(xk, w0.x, acc[0]); acc[1] = fmaf(xk, w0.y, acc[1]);
        acc[2] = fmaf(xk, w0.z, acc[2]); acc[3] = fmaf(xk, w0.w, acc[3]);
        acc[4] = fmaf(xk, w1.x, acc[4]); acc[5] = fmaf(xk, w1.y, acc[5]);
        acc[6] = fmaf(xk, w1.z, acc[6]); acc[7] = fmaf(xk, w1.w, acc[7]);
        if (RES) {
            float4 r0 = Wr4[(size_t)k * 64 + c4];
            float4 r1 = Wr4[(size_t)k * 64 + c4 + 1];
            accr[0] = fmaf(xk, r0.x, accr[0]); accr[1] = fmaf(xk, r0.y, accr[1]);
            accr[2] = fmaf(xk, r0.z, accr[2]); accr[3] = fmaf(xk, r0.w, accr[3]);
            accr[4] = fmaf(xk, r1.x, accr[4]); accr[5] = fmaf(xk, r1.y, accr[5]);
            accr[6] = fmaf(xk, r1.z, accr[6]); accr[7] = fmaf(xk, r1.w, accr[7]);
        }
    }

    float4* fto = (float4*)(ft + (size_t)row * FDIM);
    fto[c4]     = make_float4(acc[0], acc[1], acc[2], acc[3]);
    fto[c4 + 1] = make_float4(acc[4], acc[5], acc[6], acc[7]);
    if (RES) {
        float4* ro = (float4*)(resout + (size_t)row * FDIM);
        ro[c4]     = make_float4(accr[0], accr[1], accr[2], accr[3]);
        ro[c4 + 1] = make_float4(accr[4], accr[5], accr[6], accr[7]);
    }

    // attention logits: head h = lane>>3, dims [ (lane&7)*8 .. +8 )
    const int h  = lane >> 3;
    const int db = (lane & 7) * 8;
    float sl = 0.f, sr = 0.f;
    #pragma unroll
    for (int j = 0; j < 8; j++) {
        sl = fmaf(acc[j], al[h * 64 + db + j], sl);
        sr = fmaf(acc[j], ar[h * 64 + db + j], sr);
    }
    #pragma unroll
    for (int o = 4; o; o >>= 1) {
        sl += __shfl_down_sync(0xffffffffu, sl, o);
        sr += __shfl_down_sync(0xffffffffu, sr, o);
    }
    if ((lane & 7) == 0) {
        el[row * 4 + h] = sl;
        er[row * 4 + h] = sr;
    }
}

// ---------------- per-destination softmax aggregation ----------------
// One warp per dst node. Pass 1: warp-parallel max over incident edges.
// Pass 2: sequential over edges, den += ex and acc += ex*ft[src] (32 lanes x 8 feats).
// out = acc/den + residual [+ relu] ; MODE 1 additionally head-means into hf[64].
template <int MODE>  // 0: relu, write [N,256] ; 1: final, write head-mean [N,64]
__global__ void __launch_bounds__(256) agg_kernel(
    const int* __restrict__ off, const int* __restrict__ esrc,
    const float* __restrict__ el, const float* __restrict__ er,
    const float* __restrict__ ft, const float* __restrict__ resid,
    float* __restrict__ out, int n)
{
    int nid  = (blockIdx.x * 256 + threadIdx.x) >> 5;
    int lane = threadIdx.x & 31;
    if (nid >= n) return;

    int s = off[nid], eEnd = off[nid + 1];
    float4 er4 = ((const float4*)er)[nid];

    float mx0 = -1e30f, mx1 = -1e30f, mx2 = -1e30f, mx3 = -1e30f;
    for (int i = s + lane; i < eEnd; i += 32) {
        int sc = esrc[i];
        float4 e4 = ((const float4*)el)[sc];
        mx0 = fmaxf(mx0, lrelu(e4.x + er4.x));
        mx1 = fmaxf(mx1, lrelu(e4.y + er4.y));
        mx2 = fmaxf(mx2, lrelu(e4.z + er4.z));
        mx3 = fmaxf(mx3, lrelu(e4.w + er4.w));
    }
    #pragma unroll
    for (int o = 16; o; o >>= 1) {
        mx0 = fmaxf(mx0, __shfl_xor_sync(0xffffffffu, mx0, o));
        mx1 = fmaxf(mx1, __shfl_xor_sync(0xffffffffu, mx1, o));
        mx2 = fmaxf(mx2, __shfl_xor_sync(0xffffffffu, mx2, o));
        mx3 = fmaxf(mx3, __shfl_xor_sync(0xffffffffu, mx3, o));
    }

    const int h   = lane >> 3;
    float m_h  = (h == 0) ? mx0 : (h == 1) ? mx1 : (h == 2) ? mx2 : mx3;
    float er_h = (h == 0) ? er4.x : (h == 1) ? er4.y : (h == 2) ? er4.z : er4.w;

    float den = 0.f;
    float acc[8];
    #pragma unroll
    for (int j = 0; j < 8; j++) acc[j] = 0.f;

    const float4* ft4 = (const float4*)ft;
    for (int i = s; i < eEnd; i++) {
        int sc = __ldg(esrc + i);
        float ev = lrelu(__ldg(el + sc * 4 + h) + er_h);
        float ex = __expf(ev - m_h);
        den += ex;
        size_t b = (size_t)sc * 64 + lane * 2;
        float4 a  = ft4[b];
        float4 bq = ft4[b + 1];
        acc[0] = fmaf(ex, a.x,  acc[0]); acc[1] = fmaf(ex, a.y,  acc[1]);
        acc[2] = fmaf(ex, a.z,  acc[2]); acc[3] = fmaf(ex, a.w,  acc[3]);
        acc[4] = fmaf(ex, bq.x, acc[4]); acc[5] = fmaf(ex, bq.y, acc[5]);
        acc[6] = fmaf(ex, bq.z, acc[6]); acc[7] = fmaf(ex, bq.w, acc[7]);
    }
    float inv = (eEnd > s) ? (1.0f / den) : 0.f;

    const float4* rb = (const float4*)(resid + (size_t)nid * FDIM);
    float4 r0 = rb[lane * 2], r1 = rb[lane * 2 + 1];
    float v[8];
    v[0] = fmaf(acc[0], inv, r0.x); v[1] = fmaf(acc[1], inv, r0.y);
    v[2] = fmaf(acc[2], inv, r0.z); v[3] = fmaf(acc[3], inv, r0.w);
    v[4] = fmaf(acc[4], inv, r1.x); v[5] = fmaf(acc[5], inv, r1.y);
    v[6] = fmaf(acc[6], inv, r1.z); v[7] = fmaf(acc[7], inv, r1.w);

    if (MODE == 0) {
        #pragma unroll
        for (int j = 0; j < 8; j++) v[j] = fmaxf(v[j], 0.f);
        float4* ob = (float4*)(out + (size_t)nid * FDIM);
        ob[lane * 2]     = make_float4(v[0], v[1], v[2], v[3]);
        ob[lane * 2 + 1] = make_float4(v[4], v[5], v[6], v[7]);
    } else {
        // mean over heads: lanes {l, l+8, l+16, l+24} hold the same 8 dims for heads 0..3
        #pragma unroll
        for (int j = 0; j < 8; j++) {
            v[j] += __shfl_xor_sync(0xffffffffu, v[j], 8);
            v[j] += __shfl_xor_sync(0xffffffffu, v[j], 16);
            v[j] *= 0.25f;
        }
        if (lane < 8) {
            float4* ob = (float4*)(out + (size_t)nid * 64);
            ob[lane * 2]     = make_float4(v[0], v[1], v[2], v[3]);
            ob[lane * 2 + 1] = make_float4(v[4], v[5], v[6], v[7]);
        }
    }
}

// ---------------- edge scoring MLP ----------------
__global__ void __launch_bounds__(256) mlp_kernel(
    const float* __restrict__ hf, const int* __restrict__ src,
    const int* __restrict__ dst, const float* __restrict__ Wm1,
    const float* __restrict__ bm1, const float* __restrict__ Wm2,
    const float* __restrict__ bm2, float* __restrict__ out, int e)
{
    __shared__ float sW[64 * 64];
    __shared__ float sb[64];
    __shared__ float sW2[64];
    __shared__ float sdiff[8][64];
    for (int i = threadIdx.x; i < 64 * 64; i += 256) sW[i] = Wm1[i];
    if (threadIdx.x < 64) { sb[threadIdx.x] = bm1[threadIdx.x]; sW2[threadIdx.x] = Wm2[threadIdx.x]; }
    __syncthreads();
    float b2 = bm2[0];

    int warp = threadIdx.x >> 5, lane = threadIdx.x & 31;
    int wid = blockIdx.x * 8 + warp;
    int nwarps = gridDim.x * 8;

    for (int eid = wid; eid < e; eid += nwarps) {
        int s = src[eid], d = dst[eid];
        float a0 = hf[(size_t)s * 64 + lane]      - hf[(size_t)d * 64 + lane];
        float a1 = hf[(size_t)s * 64 + 32 + lane] - hf[(size_t)d * 64 + 32 + lane];
        sdiff[warp][lane]      = fabsf(a0);
        sdiff[warp][lane + 32] = fabsf(a1);
        __syncwarp();
        float z0 = sb[lane], z1 = sb[lane + 32];
        #pragma unroll
        for (int i = 0; i < 64; i++) {
            float dv = sdiff[warp][i];
            z0 = fmaf(dv, sW[i * 64 + lane],      z0);
            z1 = fmaf(dv, sW[i * 64 + 32 + lane], z1);
        }
        float sc = fmaxf(z0, 0.f) * sW2[lane] + fmaxf(z1, 0.f) * sW2[lane + 32];
        #pragma unroll
        for (int o = 16; o; o >>= 1) sc += __shfl_xor_sync(0xffffffffu, sc, o);
        if (lane == 0) out[eid] = 1.0f / (1.0f + __expf(-(sc + b2)));
        __syncwarp();
    }
}

// ---------------- launch ----------------
extern "C" void kernel_launch(void* const* d_in, const int* in_sizes, int n_in,
                              void* d_out, int out_size)
{
    const float* h   = (const float*)d_in[0];
    const int*   src = (const int*)d_in[1];
    const int*   dst = (const int*)d_in[2];
    const float* W1  = (const float*)d_in[3];
    const float* Wr1 = (const float*)d_in[4];
    const float* al1 = (const float*)d_in[5];
    const float* ar1 = (const float*)d_in[6];
    const float* W2  = (const float*)d_in[7];
    const float* al2 = (const float*)d_in[8];
    const float* ar2 = (const float*)d_in[9];
    const float* W3  = (const float*)d_in[10];
    const float* al3 = (const float*)d_in[11];
    const float* ar3 = (const float*)d_in[12];
    const float* Wm1 = (const float*)d_in[13];
    const float* bm1 = (const float*)d_in[14];
    const float* Wm2 = (const float*)d_in[15];
    const float* bm2 = (const float*)d_in[16];
    float* out = (float*)d_out;

    const int n = in_sizes[0] / 128;   // 50000
    const int e = in_sizes[1];         // 800000

    float *ft, *x, *res, *el, *er, *hfp;
    int *deg, *off, *pos, *esrc;
    cudaGetSymbolAddress((void**)&ft,   g_ft);
    cudaGetSymbolAddress((void**)&x,    g_x);
    cudaGetSymbolAddress((void**)&res,  g_res);
    cudaGetSymbolAddress((void**)&el,   g_el);
    cudaGetSymbolAddress((void**)&er,   g_er);
    cudaGetSymbolAddress((void**)&hfp,  g_hf);
    cudaGetSymbolAddress((void**)&deg,  g_deg);
    cudaGetSymbolAddress((void**)&off,  g_off);
    cudaGetSymbolAddress((void**)&pos,  g_pos);
    cudaGetSymbolAddress((void**)&esrc, g_esrc);

    // CSR build (dst-sorted edges)
    zero_int_kernel<<<(n + 1 + 255) / 256, 256>>>(deg, n + 1);
    hist_kernel<<<(e + 255) / 256, 256>>>(dst, deg, e);
    scan_kernel<<<1, 1024>>>(deg, off, pos, n);
    scatter_kernel<<<(e + 255) / 256, 256>>>(src, dst, pos, esrc, e);

    const int gb = (n + 7) / 8;  // 8 warps/block, warp-per-row

    // Layer 1
    gemm_kernel<128, true><<<gb, 256>>>(h, W1, Wr1, al1, ar1, ft, res, el, er, n);
    agg_kernel<0><<<gb, 256>>>(off, esrc, el, er, ft, res, x, n);
    // Layer 2 (identity residual, in-place)
    gemm_kernel<256, false><<<gb, 256>>>(x, W2, nullptr, al2, ar2, ft, nullptr, el, er, n);
    agg_kernel<0><<<gb, 256>>>(off, esrc, el, er, ft, x, x, n);
    // Layer 3 (identity residual, no activation, fused head-mean -> hf)
    gemm_kernel<256, false><<<gb, 256>>>(x, W3, nullptr, al3, ar3, ft, nullptr, el, er, n);
    agg_kernel<1><<<gb, 256>>>(off, esrc, el, er, ft, x, hfp, n);

    // Edge MLP -> scores
    mlp_kernel<<<1184, 256>>>(hfp, src, dst, Wm1, bm1, Wm2, bm2, out, e);
}

// round 2
// speedup vs baseline: 2.5498x; 2.5498x over previous
#include <cuda_runtime.h>
#include <math.h>

#define NN 50000
#define EE 800000
#define FDIM 256   /* HEADS*HID */

// ---------------- scratch (device globals: allowed) ----------------
__device__ float g_ft[(size_t)NN * FDIM];   // per-layer transformed features
__device__ float g_x [(size_t)NN * FDIM];   // layer activations
__device__ float g_res[(size_t)NN * FDIM];  // layer-1 residual (h @ Wr1)
__device__ float g_el[NN * 4];
__device__ float g_er[NN * 4];
__device__ float g_hf[NN * 64];
__device__ int   g_deg[NN + 1];
__device__ int   g_off[NN + 1];
__device__ int   g_pos[NN];
__device__ int   g_esrc[EE];

__device__ __forceinline__ float lrelu(float x) { return x > 0.f ? x : 0.2f * x; }

// ---------------- CSR build ----------------
__global__ void zero_int_kernel(int* __restrict__ p, int n) {
    int i = blockIdx.x * blockDim.x + threadIdx.x;
    if (i < n) p[i] = 0;
}

__global__ void hist_kernel(const int* __restrict__ dst, int* __restrict__ deg, int e) {
    int i = blockIdx.x * blockDim.x + threadIdx.x;
    if (i < e) atomicAdd(&deg[dst[i]], 1);
}

__global__ void scan_kernel(const int* __restrict__ deg, int* __restrict__ off,
                            int* __restrict__ pos, int n) {
    __shared__ int sh[1024];
    int running = 0;
    for (int base = 0; base < n; base += 1024) {
        int i = base + threadIdx.x;
        int v = (i < n) ? deg[i] : 0;
        sh[threadIdx.x] = v;
        __syncthreads();
        for (int o = 1; o < 1024; o <<= 1) {
            int t = (threadIdx.x >= o) ? sh[threadIdx.x - o] : 0;
            __syncthreads();
            sh[threadIdx.x] += t;
            __syncthreads();
        }
        int excl = sh[threadIdx.x] - v;
        if (i < n) { off[i] = running + excl; pos[i] = running + excl; }
        running += sh[1023];
        __syncthreads();
    }
    if (threadIdx.x == 0) off[n] = running;
}

__global__ void scatter_kernel(const int* __restrict__ src, const int* __restrict__ dst,
                               int* __restrict__ pos, int* __restrict__ esrc, int e) {
    int i = blockIdx.x * blockDim.x + threadIdx.x;
    if (i < e) {
        int p = atomicAdd(&pos[dst[i]], 1);
        esrc[p] = src[i];
    }
}

// ---------------- tiled GEMM: Y[M,256] = X[M,K] @ W[K,256] ----------------
// BM=128, BN=128, BK=32. 256 threads, 8x8 register tile per thread.
// Thread (tx,ty): rows bm+ty*8..+8, cols bn + {tx*4..+4, 64+tx*4..+4}.
template <int K>
__global__ void __launch_bounds__(256) gemm_tiled(
    const float* __restrict__ X, const float* __restrict__ W,
    float* __restrict__ Y, int M)
{
    __shared__ float sX[32][132];   // [k][m], pad to reduce store conflicts
    __shared__ float sW[32][128];   // [k][n]

    const int t  = threadIdx.x;
    const int tx = t & 15;
    const int ty = t >> 4;
    const int bm = blockIdx.x * 128;
    const int bn = blockIdx.y * 128;

    float acc[8][8];
    #pragma unroll
    for (int i = 0; i < 8; i++)
        #pragma unroll
        for (int j = 0; j < 8; j++) acc[i][j] = 0.f;

    for (int k0 = 0; k0 < K; k0 += 32) {
        // load X tile (128 rows x 32 k), transpose into sX[k][m]
        #pragma unroll
        for (int l = 0; l < 4; l++) {
            int idx = t + l * 256;           // float4 id, 0..1023
            int row = idx >> 3;              // 8 float4 per row
            int kk  = (idx & 7) * 4;
            int gr  = bm + row;
            float4 v = (gr < M) ? *(const float4*)(X + (size_t)gr * K + k0 + kk)
                                : make_float4(0.f, 0.f, 0.f, 0.f);
            sX[kk + 0][row] = v.x; sX[kk + 1][row] = v.y;
            sX[kk + 2][row] = v.z; sX[kk + 3][row] = v.w;
        }
        // load W tile (32 k x 128 n)
        #pragma unroll
        for (int l = 0; l < 4; l++) {
            int idx = t + l * 256;
            int kk  = idx >> 5;              // 32 float4 per k-row
            int nn  = (idx & 31) * 4;
            *(float4*)&sW[kk][nn] =
                *(const float4*)(W + (size_t)(k0 + kk) * 256 + bn + nn);
        }
        __syncthreads();

        #pragma unroll
        for (int k = 0; k < 32; k++) {
            float4 a0 = *(const float4*)&sX[k][ty * 8];
            float4 a1 = *(const float4*)&sX[k][ty * 8 + 4];
            float4 b0 = *(const float4*)&sW[k][tx * 4];
            float4 b1 = *(const float4*)&sW[k][64 + tx * 4];
            float a[8] = {a0.x, a0.y, a0.z, a0.w, a1.x, a1.y, a1.z, a1.w};
            float b[8] = {b0.x, b0.y, b0.z, b0.w, b1.x, b1.y, b1.z, b1.w};
            #pragma unroll
            for (int i = 0; i < 8; i++)
                #pragma unroll
                for (int j = 0; j < 8; j++)
                    acc[i][j] = fmaf(a[i], b[j], acc[i][j]);
        }
        __syncthreads();
    }

    #pragma unroll
    for (int i = 0; i < 8; i++) {
        int gr = bm + ty * 8 + i;
        if (gr < M) {
            float4* yb = (float4*)(Y + (size_t)gr * 256 + bn);
            yb[tx]      = make_float4(acc[i][0], acc[i][1], acc[i][2], acc[i][3]);
            yb[16 + tx] = make_float4(acc[i][4], acc[i][5], acc[i][6], acc[i][7]);
        }
    }
}

// ---------------- attention logits from ft ----------------
__global__ void __launch_bounds__(256) elr_kernel(
    const float* __restrict__ ft, const float* __restrict__ al,
    const float* __restrict__ ar, float* __restrict__ el,
    float* __restrict__ er, int n)
{
    int row  = (blockIdx.x * 256 + threadIdx.x) >> 5;
    int lane = threadIdx.x & 31;
    if (row >= n) return;

    const float4* fb = (const float4*)(ft + (size_t)row * FDIM);
    float4 f0 = fb[lane * 2], f1 = fb[lane * 2 + 1];
    float f[8] = {f0.x, f0.y, f0.z, f0.w, f1.x, f1.y, f1.z, f1.w};

    const int h  = lane >> 3;
    const int db = (lane & 7) * 8;
    float sl = 0.f, sr = 0.f;
    #pragma unroll
    for (int j = 0; j < 8; j++) {
        sl = fmaf(f[j], al[h * 64 + db + j], sl);
        sr = fmaf(f[j], ar[h * 64 + db + j], sr);
    }
    #pragma unroll
    for (int o = 4; o; o >>= 1) {
        sl += __shfl_down_sync(0xffffffffu, sl, o);
        sr += __shfl_down_sync(0xffffffffu, sr, o);
    }
    if ((lane & 7) == 0) {
        el[row * 4 + h] = sl;
        er[row * 4 + h] = sr;
    }
}

// ---------------- per-destination softmax aggregation ----------------
template <int MODE>  // 0: relu, write [N,256] ; 1: final, head-mean -> [N,64]
__global__ void __launch_bounds__(256) agg_kernel(
    const int* __restrict__ off, const int* __restrict__ esrc,
    const float* __restrict__ el, const float* __restrict__ er,
    const float* __restrict__ ft, const float* __restrict__ resid,
    float* __restrict__ out, int n)
{
    int nid  = (blockIdx.x * 256 + threadIdx.x) >> 5;
    int lane = threadIdx.x & 31;
    if (nid >= n) return;

    int s = off[nid], eEnd = off[nid + 1];
    float4 er4 = ((const float4*)er)[nid];

    // pass 1: per-head max (warp-parallel)
    float mx0 = -1e30f, mx1 = -1e30f, mx2 = -1e30f, mx3 = -1e30f;
    for (int i = s + lane; i < eEnd; i += 32) {
        int sc = esrc[i];
        float4 e4 = ((const float4*)el)[sc];
        mx0 = fmaxf(mx0, lrelu(e4.x + er4.x));
        mx1 = fmaxf(mx1, lrelu(e4.y + er4.y));
        mx2 = fmaxf(mx2, lrelu(e4.z + er4.z));
        mx3 = fmaxf(mx3, lrelu(e4.w + er4.w));
    }
    #pragma unroll
    for (int o = 16; o; o >>= 1) {
        mx0 = fmaxf(mx0, __shfl_xor_sync(0xffffffffu, mx0, o));
        mx1 = fmaxf(mx1, __shfl_xor_sync(0xffffffffu, mx1, o));
        mx2 = fmaxf(mx2, __shfl_xor_sync(0xffffffffu, mx2, o));
        mx3 = fmaxf(mx3, __shfl_xor_sync(0xffffffffu, mx3, o));
    }

    const int h   = lane >> 3;
    float m_h  = (h == 0) ? mx0 : (h == 1) ? mx1 : (h == 2) ? mx2 : mx3;
    float er_h = (h == 0) ? er4.x : (h == 1) ? er4.y : (h == 2) ? er4.z : er4.w;

    float den = 0.f;
    float acc[8];
    #pragma unroll
    for (int j = 0; j < 8; j++) acc[j] = 0.f;

    const float4* ft4 = (const float4*)ft;

    // pass 2: unroll by 2 for load-latency overlap
    int i = s;
    for (; i + 1 < eEnd; i += 2) {
        int sc0 = __ldg(esrc + i);
        int sc1 = __ldg(esrc + i + 1);
        float e0 = __ldg(el + sc0 * 4 + h);
        float e1 = __ldg(el + sc1 * 4 + h);
        size_t b0 = (size_t)sc0 * 64 + lane * 2;
        size_t b1 = (size_t)sc1 * 64 + lane * 2;
        float4 a0 = ft4[b0], a1 = ft4[b0 + 1];
        float4 c0 = ft4[b1], c1 = ft4[b1 + 1];
        float ex0 = __expf(lrelu(e0 + er_h) - m_h);
        float ex1 = __expf(lrelu(e1 + er_h) - m_h);
        den += ex0 + ex1;
        acc[0] = fmaf(ex0, a0.x, acc[0]); acc[1] = fmaf(ex0, a0.y, acc[1]);
        acc[2] = fmaf(ex0, a0.z, acc[2]); acc[3] = fmaf(ex0, a0.w, acc[3]);
        acc[4] = fmaf(ex0, a1.x, acc[4]); acc[5] = fmaf(ex0, a1.y, acc[5]);
        acc[6] = fmaf(ex0, a1.z, acc[6]); acc[7] = fmaf(ex0, a1.w, acc[7]);
        acc[0] = fmaf(ex1, c0.x, acc[0]); acc[1] = fmaf(ex1, c0.y, acc[1]);
        acc[2] = fmaf(ex1, c0.z, acc[2]); acc[3] = fmaf(ex1, c0.w, acc[3]);
        acc[4] = fmaf(ex1, c1.x, acc[4]); acc[5] = fmaf(ex1, c1.y, acc[5]);
        acc[6] = fmaf(ex1, c1.z, acc[6]); acc[7] = fmaf(ex1, c1.w, acc[7]);
    }
    if (i < eEnd) {
        int sc = __ldg(esrc + i);
        float ev = lrelu(__ldg(el + sc * 4 + h) + er_h);
        float ex = __expf(ev - m_h);
        den += ex;
        size_t b = (size_t)sc * 64 + lane * 2;
        float4 a = ft4[b], c = ft4[b + 1];
        acc[0] = fmaf(ex, a.x, acc[0]); acc[1] = fmaf(ex, a.y, acc[1]);
        acc[2] = fmaf(ex, a.z, acc[2]); acc[3] = fmaf(ex, a.w, acc[3]);
        acc[4] = fmaf(ex, c.x, acc[4]); acc[5] = fmaf(ex, c.y, acc[5]);
        acc[6] = fmaf(ex, c.z, acc[6]); acc[7] = fmaf(ex, c.w, acc[7]);
    }

    float inv = (eEnd > s) ? (1.0f / den) : 0.f;

    const float4* rb = (const float4*)(resid + (size_t)nid * FDIM);
    float4 r0 = rb[lane * 2], r1 = rb[lane * 2 + 1];
    float v[8];
    v[0] = fmaf(acc[0], inv, r0.x); v[1] = fmaf(acc[1], inv, r0.y);
    v[2] = fmaf(acc[2], inv, r0.z); v[3] = fmaf(acc[3], inv, r0.w);
    v[4] = fmaf(acc[4], inv, r1.x); v[5] = fmaf(acc[5], inv, r1.y);
    v[6] = fmaf(acc[6], inv, r1.z); v[7] = fmaf(acc[7], inv, r1.w);

    if (MODE == 0) {
        #pragma unroll
        for (int j = 0; j < 8; j++) v[j] = fmaxf(v[j], 0.f);
        float4* ob = (float4*)(out + (size_t)nid * FDIM);
        ob[lane * 2]     = make_float4(v[0], v[1], v[2], v[3]);
        ob[lane * 2 + 1] = make_float4(v[4], v[5], v[6], v[7]);
    } else {
        #pragma unroll
        for (int j = 0; j < 8; j++) {
            v[j] += __shfl_xor_sync(0xffffffffu, v[j], 8);
            v[j] += __shfl_xor_sync(0xffffffffu, v[j], 16);
            v[j] *= 0.25f;
        }
        if (lane < 8) {
            float4* ob = (float4*)(out + (size_t)nid * 64);
            ob[lane * 2]     = make_float4(v[0], v[1], v[2], v[3]);
            ob[lane * 2 + 1] = make_float4(v[4], v[5], v[6], v[7]);
        }
    }
}

// ---------------- edge scoring MLP (2 edges per warp iteration) ----------------
__global__ void __launch_bounds__(256) mlp_kernel(
    const float* __restrict__ hf, const int* __restrict__ src,
    const int* __restrict__ dst, const float* __restrict__ Wm1,
    const float* __restrict__ bm1, const float* __restrict__ Wm2,
    const float* __restrict__ bm2, float* __restrict__ out, int e)
{
    __shared__ float sW[64 * 64];
    __shared__ float sb[64];
    __shared__ float sW2[64];
    __shared__ float sdiff[8][2][64];
    for (int i = threadIdx.x; i < 64 * 64; i += 256) sW[i] = Wm1[i];
    if (threadIdx.x < 64) { sb[threadIdx.x] = bm1[threadIdx.x]; sW2[threadIdx.x] = Wm2[threadIdx.x]; }
    __syncthreads();
    float b2 = bm2[0];

    int warp = threadIdx.x >> 5, lane = threadIdx.x & 31;
    int wid = blockIdx.x * 8 + warp;
    int nwarps = gridDim.x * 8;

    for (int p = wid; p * 2 < e; p += nwarps) {
        int e0 = p * 2, e1 = p * 2 + 1;
        bool two = (e1 < e);
        {
            int s0 = src[e0], d0 = dst[e0];
            sdiff[warp][0][lane]      = fabsf(hf[(size_t)s0 * 64 + lane]      - hf[(size_t)d0 * 64 + lane]);
            sdiff[warp][0][lane + 32] = fabsf(hf[(size_t)s0 * 64 + 32 + lane] - hf[(size_t)d0 * 64 + 32 + lane]);
        }
        if (two) {
            int s1 = src[e1], d1 = dst[e1];
            sdiff[warp][1][lane]      = fabsf(hf[(size_t)s1 * 64 + lane]      - hf[(size_t)d1 * 64 + lane]);
            sdiff[warp][1][lane + 32] = fabsf(hf[(size_t)s1 * 64 + 32 + lane] - hf[(size_t)d1 * 64 + 32 + lane]);
        }
        __syncwarp();

        float z00 = sb[lane], z01 = sb[lane + 32];
        float z10 = z00, z11 = z01;
        #pragma unroll
        for (int i = 0; i < 64; i++) {
            float w0 = sW[i * 64 + lane];
            float w1 = sW[i * 64 + 32 + lane];
            float d0 = sdiff[warp][0][i];
            float d1 = sdiff[warp][1][i];
            z00 = fmaf(d0, w0, z00); z01 = fmaf(d0, w1, z01);
            z10 = fmaf(d1, w0, z10); z11 = fmaf(d1, w1, z11);
        }
        float sc0 = fmaxf(z00, 0.f) * sW2[lane] + fmaxf(z01, 0.f) * sW2[lane + 32];
        float sc1 = fmaxf(z10, 0.f) * sW2[lane] + fmaxf(z11, 0.f) * sW2[lane + 32];
        #pragma unroll
        for (int o = 16; o; o >>= 1) {
            sc0 += __shfl_xor_sync(0xffffffffu, sc0, o);
            sc1 += __shfl_xor_sync(0xffffffffu, sc1, o);
        }
        if (lane == 0) out[e0] = 1.0f / (1.0f + __expf(-(sc0 + b2)));
        if (two && lane == 1) out[e1] = 1.0f / (1.0f + __expf(-(sc1 + b2)));
        __syncwarp();
    }
}

// ---------------- launch ----------------
extern "C" void kernel_launch(void* const* d_in, const int* in_sizes, int n_in,
                              void* d_out, int out_size)
{
    const float* h   = (const float*)d_in[0];
    const int*   src = (const int*)d_in[1];
    const int*   dst = (const int*)d_in[2];
    const float* W1  = (const float*)d_in[3];
    const float* Wr1 = (const float*)d_in[4];
    const float* al1 = (const float*)d_in[5];
    const float* ar1 = (const float*)d_in[6];
    const float* W2  = (const float*)d_in[7];
    const float* al2 = (const float*)d_in[8];
    const float* ar2 = (const float*)d_in[9];
    const float* W3  = (const float*)d_in[10];
    const float* al3 = (const float*)d_in[11];
    const float* ar3 = (const float*)d_in[12];
    const float* Wm1 = (const float*)d_in[13];
    const float* bm1 = (const float*)d_in[14];
    const float* Wm2 = (const float*)d_in[15];
    const float* bm2 = (const float*)d_in[16];
    float* out = (float*)d_out;

    const int n = in_sizes[0] / 128;   // 50000
    const int e = in_sizes[1];         // 800000

    float *ft, *x, *res, *el, *er, *hfp;
    int *deg, *off, *pos, *esrc;
    cudaGetSymbolAddress((void**)&ft,   g_ft);
    cudaGetSymbolAddress((void**)&x,    g_x);
    cudaGetSymbolAddress((void**)&res,  g_res);
    cudaGetSymbolAddress((void**)&el,   g_el);
    cudaGetSymbolAddress((void**)&er,   g_er);
    cudaGetSymbolAddress((void**)&hfp,  g_hf);
    cudaGetSymbolAddress((void**)&deg,  g_deg);
    cudaGetSymbolAddress((void**)&off,  g_off);
    cudaGetSymbolAddress((void**)&pos,  g_pos);
    cudaGetSymbolAddress((void**)&esrc, g_esrc);

    // CSR build (dst-sorted edges)
    zero_int_kernel<<<(n + 1 + 255) / 256, 256>>>(deg, n + 1);
    hist_kernel<<<(e + 255) / 256, 256>>>(dst, deg, e);
    scan_kernel<<<1, 1024>>>(deg, off, pos, n);
    scatter_kernel<<<(e + 255) / 256, 256>>>(src, dst, pos, esrc, e);

    dim3 gg((n + 127) / 128, 2);
    const int gw = (n + 7) / 8;   // warp-per-node kernels

    // Layer 1
    gemm_tiled<128><<<gg, 256>>>(h, W1,  ft,  n);
    gemm_tiled<128><<<gg, 256>>>(h, Wr1, res, n);
    elr_kernel<<<gw, 256>>>(ft, al1, ar1, el, er, n);
    agg_kernel<0><<<gw, 256>>>(off, esrc, el, er, ft, res, x, n);
    // Layer 2 (identity residual)
    gemm_tiled<256><<<gg, 256>>>(x, W2, ft, n);
    elr_kernel<<<gw, 256>>>(ft, al2, ar2, el, er, n);
    agg_kernel<0><<<gw, 256>>>(off, esrc, el, er, ft, x, x, n);
    // Layer 3 (identity residual, no activation, head-mean -> hf)
    gemm_tiled<256><<<gg, 256>>>(x, W3, ft, n);
    elr_kernel<<<gw, 256>>>(ft, al3, ar3, el, er, n);
    agg_kernel<1><<<gw, 256>>>(off, esrc, el, er, ft, x, hfp, n);

    // Edge MLP -> scores
    mlp_kernel<<<1184, 256>>>(hfp, src, dst, Wm1, bm1, Wm2, bm2, out, e);
}

// round 3
// speedup vs baseline: 2.9101x; 1.1413x over previous
#include <cuda_runtime.h>
#include <math.h>

#define NN 50000
#define EE 800000
#define FDIM 256   /* HEADS*HID */

// ---------------- scratch (device globals: allowed) ----------------
__device__ float g_ft[(size_t)NN * FDIM];   // per-layer transformed features
__device__ float g_x [(size_t)NN * FDIM];   // layer activations
__device__ float g_res[(size_t)NN * FDIM];  // layer-1 residual (h @ Wr1)
__device__ float g_el[NN * 4];
__device__ float g_er[NN * 4];
__device__ float g_hf[NN * 64];
__device__ int   g_deg[NN + 1];
__device__ int   g_off[NN + 1];
__device__ int   g_pos[NN];
__device__ int   g_esrc[EE];

__device__ __forceinline__ float lrelu(float x) { return x > 0.f ? x : 0.2f * x; }

// ---------------- CSR build ----------------
__global__ void zero_int_kernel(int* __restrict__ p, int n) {
    int i = blockIdx.x * blockDim.x + threadIdx.x;
    if (i < n) p[i] = 0;
}

__global__ void hist_kernel(const int* __restrict__ dst, int* __restrict__ deg, int e) {
    int i = blockIdx.x * blockDim.x + threadIdx.x;
    if (i < e) atomicAdd(&deg[dst[i]], 1);
}

__global__ void scan_kernel(const int* __restrict__ deg, int* __restrict__ off,
                            int* __restrict__ pos, int n) {
    __shared__ int sh[1024];
    int running = 0;
    for (int base = 0; base < n; base += 1024) {
        int i = base + threadIdx.x;
        int v = (i < n) ? deg[i] : 0;
        sh[threadIdx.x] = v;
        __syncthreads();
        for (int o = 1; o < 1024; o <<= 1) {
            int t = (threadIdx.x >= o) ? sh[threadIdx.x - o] : 0;
            __syncthreads();
            sh[threadIdx.x] += t;
            __syncthreads();
        }
        int excl = sh[threadIdx.x] - v;
        if (i < n) { off[i] = running + excl; pos[i] = running + excl; }
        running += sh[1023];
        __syncthreads();
    }
    if (threadIdx.x == 0) off[n] = running;
}

__global__ void scatter_kernel(const int* __restrict__ src, const int* __restrict__ dst,
                               int* __restrict__ pos, int* __restrict__ esrc, int e) {
    int i = blockIdx.x * blockDim.x + threadIdx.x;
    if (i < e) {
        int p = atomicAdd(&pos[dst[i]], 1);
        esrc[p] = src[i];
    }
}

// ---------------- tiled GEMM: Y[M,256] = X[M,K] @ W[K,256] ----------------
template <int K>
__global__ void __launch_bounds__(256) gemm_tiled(
    const float* __restrict__ X, const float* __restrict__ W,
    float* __restrict__ Y, int M)
{
    __shared__ float sX[32][132];
    __shared__ float sW[32][128];

    const int t  = threadIdx.x;
    const int tx = t & 15;
    const int ty = t >> 4;
    const int bm = blockIdx.x * 128;
    const int bn = blockIdx.y * 128;

    float acc[8][8];
    #pragma unroll
    for (int i = 0; i < 8; i++)
        #pragma unroll
        for (int j = 0; j < 8; j++) acc[i][j] = 0.f;

    for (int k0 = 0; k0 < K; k0 += 32) {
        #pragma unroll
        for (int l = 0; l < 4; l++) {
            int idx = t + l * 256;
            int row = idx >> 3;
            int kk  = (idx & 7) * 4;
            int gr  = bm + row;
            float4 v = (gr < M) ? *(const float4*)(X + (size_t)gr * K + k0 + kk)
                                : make_float4(0.f, 0.f, 0.f, 0.f);
            sX[kk + 0][row] = v.x; sX[kk + 1][row] = v.y;
            sX[kk + 2][row] = v.z; sX[kk + 3][row] = v.w;
        }
        #pragma unroll
        for (int l = 0; l < 4; l++) {
            int idx = t + l * 256;
            int kk  = idx >> 5;
            int nn  = (idx & 31) * 4;
            *(float4*)&sW[kk][nn] =
                *(const float4*)(W + (size_t)(k0 + kk) * 256 + bn + nn);
        }
        __syncthreads();

        #pragma unroll
        for (int k = 0; k < 32; k++) {
            float4 a0 = *(const float4*)&sX[k][ty * 8];
            float4 a1 = *(const float4*)&sX[k][ty * 8 + 4];
            float4 b0 = *(const float4*)&sW[k][tx * 4];
            float4 b1 = *(const float4*)&sW[k][64 + tx * 4];
            float a[8] = {a0.x, a0.y, a0.z, a0.w, a1.x, a1.y, a1.z, a1.w};
            float b[8] = {b0.x, b0.y, b0.z, b0.w, b1.x, b1.y, b1.z, b1.w};
            #pragma unroll
            for (int i = 0; i < 8; i++)
                #pragma unroll
                for (int j = 0; j < 8; j++)
                    acc[i][j] = fmaf(a[i], b[j], acc[i][j]);
        }
        __syncthreads();
    }

    #pragma unroll
    for (int i = 0; i < 8; i++) {
        int gr = bm + ty * 8 + i;
        if (gr < M) {
            float4* yb = (float4*)(Y + (size_t)gr * 256 + bn);
            yb[tx]      = make_float4(acc[i][0], acc[i][1], acc[i][2], acc[i][3]);
            yb[16 + tx] = make_float4(acc[i][4], acc[i][5], acc[i][6], acc[i][7]);
        }
    }
}

// ---------------- attention logits from ft ----------------
__global__ void __launch_bounds__(256) elr_kernel(
    const float* __restrict__ ft, const float* __restrict__ al,
    const float* __restrict__ ar, float* __restrict__ el,
    float* __restrict__ er, int n)
{
    int row  = (blockIdx.x * 256 + threadIdx.x) >> 5;
    int lane = threadIdx.x & 31;
    if (row >= n) return;

    const float4* fb = (const float4*)(ft + (size_t)row * FDIM);
    float4 f0 = fb[lane * 2], f1 = fb[lane * 2 + 1];
    float f[8] = {f0.x, f0.y, f0.z, f0.w, f1.x, f1.y, f1.z, f1.w};

    const int h  = lane >> 3;
    const int db = (lane & 7) * 8;
    float sl = 0.f, sr = 0.f;
    #pragma unroll
    for (int j = 0; j < 8; j++) {
        sl = fmaf(f[j], al[h * 64 + db + j], sl);
        sr = fmaf(f[j], ar[h * 64 + db + j], sr);
    }
    #pragma unroll
    for (int o = 4; o; o >>= 1) {
        sl += __shfl_down_sync(0xffffffffu, sl, o);
        sr += __shfl_down_sync(0xffffffffu, sr, o);
    }
    if ((lane & 7) == 0) {
        el[row * 4 + h] = sl;
        er[row * 4 + h] = sr;
    }
}

// ---------------- per-destination softmax aggregation ----------------
template <int MODE>  // 0: relu, write [N,256] ; 1: final, head-mean -> [N,64]
__global__ void __launch_bounds__(256) agg_kernel(
    const int* __restrict__ off, const int* __restrict__ esrc,
    const float* __restrict__ el, const float* __restrict__ er,
    const float* __restrict__ ft, const float* __restrict__ resid,
    float* __restrict__ out, int n)
{
    int nid  = (blockIdx.x * 256 + threadIdx.x) >> 5;
    int lane = threadIdx.x & 31;
    if (nid >= n) return;

    int s = off[nid], eEnd = off[nid + 1];
    float4 er4 = ((const float4*)er)[nid];

    float mx0 = -1e30f, mx1 = -1e30f, mx2 = -1e30f, mx3 = -1e30f;
    for (int i = s + lane; i < eEnd; i += 32) {
        int sc = esrc[i];
        float4 e4 = ((const float4*)el)[sc];
        mx0 = fmaxf(mx0, lrelu(e4.x + er4.x));
        mx1 = fmaxf(mx1, lrelu(e4.y + er4.y));
        mx2 = fmaxf(mx2, lrelu(e4.z + er4.z));
        mx3 = fmaxf(mx3, lrelu(e4.w + er4.w));
    }
    #pragma unroll
    for (int o = 16; o; o >>= 1) {
        mx0 = fmaxf(mx0, __shfl_xor_sync(0xffffffffu, mx0, o));
        mx1 = fmaxf(mx1, __shfl_xor_sync(0xffffffffu, mx1, o));
        mx2 = fmaxf(mx2, __shfl_xor_sync(0xffffffffu, mx2, o));
        mx3 = fmaxf(mx3, __shfl_xor_sync(0xffffffffu, mx3, o));
    }

    const int h   = lane >> 3;
    float m_h  = (h == 0) ? mx0 : (h == 1) ? mx1 : (h == 2) ? mx2 : mx3;
    float er_h = (h == 0) ? er4.x : (h == 1) ? er4.y : (h == 2) ? er4.z : er4.w;

    float den = 0.f;
    float acc[8];
    #pragma unroll
    for (int j = 0; j < 8; j++) acc[j] = 0.f;

    const float4* ft4 = (const float4*)ft;

    int i = s;
    for (; i + 1 < eEnd; i += 2) {
        int sc0 = __ldg(esrc + i);
        int sc1 = __ldg(esrc + i + 1);
        float e0 = __ldg(el + sc0 * 4 + h);
        float e1 = __ldg(el + sc1 * 4 + h);
        size_t b0 = (size_t)sc0 * 64 + lane * 2;
        size_t b1 = (size_t)sc1 * 64 + lane * 2;
        float4 a0 = ft4[b0], a1 = ft4[b0 + 1];
        float4 c0 = ft4[b1], c1 = ft4[b1 + 1];
        float ex0 = __expf(lrelu(e0 + er_h) - m_h);
        float ex1 = __expf(lrelu(e1 + er_h) - m_h);
        den += ex0 + ex1;
        acc[0] = fmaf(ex0, a0.x, acc[0]); acc[1] = fmaf(ex0, a0.y, acc[1]);
        acc[2] = fmaf(ex0, a0.z, acc[2]); acc[3] = fmaf(ex0, a0.w, acc[3]);
        acc[4] = fmaf(ex0, a1.x, acc[4]); acc[5] = fmaf(ex0, a1.y, acc[5]);
        acc[6] = fmaf(ex0, a1.z, acc[6]); acc[7] = fmaf(ex0, a1.w, acc[7]);
        acc[0] = fmaf(ex1, c0.x, acc[0]); acc[1] = fmaf(ex1, c0.y, acc[1]);
        acc[2] = fmaf(ex1, c0.z, acc[2]); acc[3] = fmaf(ex1, c0.w, acc[3]);
        acc[4] = fmaf(ex1, c1.x, acc[4]); acc[5] = fmaf(ex1, c1.y, acc[5]);
        acc[6] = fmaf(ex1, c1.z, acc[6]); acc[7] = fmaf(ex1, c1.w, acc[7]);
    }
    if (i < eEnd) {
        int sc = __ldg(esrc + i);
        float ev = lrelu(__ldg(el + sc * 4 + h) + er_h);
        float ex = __expf(ev - m_h);
        den += ex;
        size_t b = (size_t)sc * 64 + lane * 2;
        float4 a = ft4[b], c = ft4[b + 1];
        acc[0] = fmaf(ex, a.x, acc[0]); acc[1] = fmaf(ex, a.y, acc[1]);
        acc[2] = fmaf(ex, a.z, acc[2]); acc[3] = fmaf(ex, a.w, acc[3]);
        acc[4] = fmaf(ex, c.x, acc[4]); acc[5] = fmaf(ex, c.y, acc[5]);
        acc[6] = fmaf(ex, c.z, acc[6]); acc[7] = fmaf(ex, c.w, acc[7]);
    }

    float inv = (eEnd > s) ? (1.0f / den) : 0.f;

    const float4* rb = (const float4*)(resid + (size_t)nid * FDIM);
    float4 r0 = rb[lane * 2], r1 = rb[lane * 2 + 1];
    float v[8];
    v[0] = fmaf(acc[0], inv, r0.x); v[1] = fmaf(acc[1], inv, r0.y);
    v[2] = fmaf(acc[2], inv, r0.z); v[3] = fmaf(acc[3], inv, r0.w);
    v[4] = fmaf(acc[4], inv, r1.x); v[5] = fmaf(acc[5], inv, r1.y);
    v[6] = fmaf(acc[6], inv, r1.z); v[7] = fmaf(acc[7], inv, r1.w);

    if (MODE == 0) {
        #pragma unroll
        for (int j = 0; j < 8; j++) v[j] = fmaxf(v[j], 0.f);
        float4* ob = (float4*)(out + (size_t)nid * FDIM);
        ob[lane * 2]     = make_float4(v[0], v[1], v[2], v[3]);
        ob[lane * 2 + 1] = make_float4(v[4], v[5], v[6], v[7]);
    } else {
        #pragma unroll
        for (int j = 0; j < 8; j++) {
            v[j] += __shfl_xor_sync(0xffffffffu, v[j], 8);
            v[j] += __shfl_xor_sync(0xffffffffu, v[j], 16);
            v[j] *= 0.25f;
        }
        if (lane < 8) {
            float4* ob = (float4*)(out + (size_t)nid * 64);
            ob[lane * 2]     = make_float4(v[0], v[1], v[2], v[3]);
            ob[lane * 2 + 1] = make_float4(v[4], v[5], v[6], v[7]);
        }
    }
}

// ---------------- edge scoring MLP as register-tiled GEMM ----------------
// Block = 64 edges. sD[e][k] = |hf[src]-hf[dst]| in shared (stride 68, 16B aligned),
// Wm1 in shared. Thread (tx,ty): 4 edges (ty*4..) x 4 outs (tx*4..), 16 FMA/k.
// Epilogue: relu, dot with Wm2, half-warp shuffle reduce, sigmoid.
__global__ void __launch_bounds__(256) mlp_kernel(
    const float* __restrict__ hf, const int* __restrict__ src,
    const int* __restrict__ dst, const float* __restrict__ Wm1,
    const float* __restrict__ bm1, const float* __restrict__ Wm2,
    const float* __restrict__ bm2, float* __restrict__ out, int e)
{
    __shared__ float sD[64][68];   // [edge][k], padded: rows 16B-aligned
    __shared__ float sW[64][64];   // [k][out]
    __shared__ float sb[64];
    __shared__ float sW2[64];

    const int t    = threadIdx.x;
    const int warp = t >> 5;
    const int lane = t & 31;
    const int e0   = blockIdx.x * 64;

    for (int i = t; i < 64 * 64; i += 256) sW[i >> 6][i & 63] = Wm1[i];
    if (t < 64) { sb[t] = bm1[t]; sW2[t] = Wm2[t]; }

    // build |hf[s]-hf[d]| rows: warp w handles edges e0+w*8 .. +8
    #pragma unroll
    for (int j = 0; j < 8; j++) {
        int le  = warp * 8 + j;
        int eid = e0 + le;
        float2 dv;
        if (eid < e) {
            int s = src[eid], d = dst[eid];
            float2 a = *(const float2*)(hf + (size_t)s * 64 + lane * 2);
            float2 b = *(const float2*)(hf + (size_t)d * 64 + lane * 2);
            dv.x = fabsf(a.x - b.x);
            dv.y = fabsf(a.y - b.y);
        } else {
            dv.x = 0.f; dv.y = 0.f;
        }
        *(float2*)&sD[le][lane * 2] = dv;
    }
    __syncthreads();

    const int tx = t & 15;       // out group: cols tx*4..+3
    const int ty = t >> 4;       // edge group: edges ty*4..+3

    float z[4][4];
    #pragma unroll
    for (int i = 0; i < 4; i++)
        #pragma unroll
        for (int j = 0; j < 4; j++) z[i][j] = sb[tx * 4 + j];

    #pragma unroll 8
    for (int k = 0; k < 64; k++) {
        float4 wv = *(const float4*)&sW[k][tx * 4];
        float d0 = sD[ty * 4 + 0][k];
        float d1 = sD[ty * 4 + 1][k];
        float d2 = sD[ty * 4 + 2][k];
        float d3 = sD[ty * 4 + 3][k];
        z[0][0] = fmaf(d0, wv.x, z[0][0]); z[0][1] = fmaf(d0, wv.y, z[0][1]);
        z[0][2] = fmaf(d0, wv.z, z[0][2]); z[0][3] = fmaf(d0, wv.w, z[0][3]);
        z[1][0] = fmaf(d1, wv.x, z[1][0]); z[1][1] = fmaf(d1, wv.y, z[1][1]);
        z[1][2] = fmaf(d1, wv.z, z[1][2]); z[1][3] = fmaf(d1, wv.w, z[1][3]);
        z[2][0] = fmaf(d2, wv.x, z[2][0]); z[2][1] = fmaf(d2, wv.y, z[2][1]);
        z[2][2] = fmaf(d2, wv.z, z[2][2]); z[2][3] = fmaf(d2, wv.w, z[2][3]);
        z[3][0] = fmaf(d3, wv.x, z[3][0]); z[3][1] = fmaf(d3, wv.y, z[3][1]);
        z[3][2] = fmaf(d3, wv.z, z[3][2]); z[3][3] = fmaf(d3, wv.w, z[3][3]);
    }

    // epilogue: relu -> Wm2 -> reduce over the 16 tx groups (low 4 bits of t)
    float w2a = sW2[tx * 4 + 0], w2b = sW2[tx * 4 + 1];
    float w2c = sW2[tx * 4 + 2], w2d = sW2[tx * 4 + 3];
    float p[4];
    #pragma unroll
    for (int i = 0; i < 4; i++) {
        p[i] = fmaxf(z[i][0], 0.f) * w2a + fmaxf(z[i][1], 0.f) * w2b
             + fmaxf(z[i][2], 0.f) * w2c + fmaxf(z[i][3], 0.f) * w2d;
        #pragma unroll
        for (int o = 8; o; o >>= 1) p[i] += __shfl_xor_sync(0xffffffffu, p[i], o);
    }
    if (tx == 0) {
        float b2 = bm2[0];
        #pragma unroll
        for (int i = 0; i < 4; i++) {
            int eid = e0 + ty * 4 + i;
            if (eid < e) out[eid] = 1.0f / (1.0f + __expf(-(p[i] + b2)));
        }
    }
}

// ---------------- launch ----------------
extern "C" void kernel_launch(void* const* d_in, const int* in_sizes, int n_in,
                              void* d_out, int out_size)
{
    const float* h   = (const float*)d_in[0];
    const int*   src = (const int*)d_in[1];
    const int*   dst = (const int*)d_in[2];
    const float* W1  = (const float*)d_in[3];
    const float* Wr1 = (const float*)d_in[4];
    const float* al1 = (const float*)d_in[5];
    const float* ar1 = (const float*)d_in[6];
    const float* W2  = (const float*)d_in[7];
    const float* al2 = (const float*)d_in[8];
    const float* ar2 = (const float*)d_in[9];
    const float* W3  = (const float*)d_in[10];
    const float* al3 = (const float*)d_in[11];
    const float* ar3 = (const float*)d_in[12];
    const float* Wm1 = (const float*)d_in[13];
    const float* bm1 = (const float*)d_in[14];
    const float* Wm2 = (const float*)d_in[15];
    const float* bm2 = (const float*)d_in[16];
    float* out = (float*)d_out;

    const int n = in_sizes[0] / 128;   // 50000
    const int e = in_sizes[1];         // 800000

    float *ft, *x, *res, *el, *er, *hfp;
    int *deg, *off, *pos, *esrc;
    cudaGetSymbolAddress((void**)&ft,   g_ft);
    cudaGetSymbolAddress((void**)&x,    g_x);
    cudaGetSymbolAddress((void**)&res,  g_res);
    cudaGetSymbolAddress((void**)&el,   g_el);
    cudaGetSymbolAddress((void**)&er,   g_er);
    cudaGetSymbolAddress((void**)&hfp,  g_hf);
    cudaGetSymbolAddress((void**)&deg,  g_deg);
    cudaGetSymbolAddress((void**)&off,  g_off);
    cudaGetSymbolAddress((void**)&pos,  g_pos);
    cudaGetSymbolAddress((void**)&esrc, g_esrc);

    // CSR build (dst-sorted edges)
    zero_int_kernel<<<(n + 1 + 255) / 256, 256>>>(deg, n + 1);
    hist_kernel<<<(e + 255) / 256, 256>>>(dst, deg, e);
    scan_kernel<<<1, 1024>>>(deg, off, pos, n);
    scatter_kernel<<<(e + 255) / 256, 256>>>(src, dst, pos, esrc, e);

    dim3 gg((n + 127) / 128, 2);
    const int gw = (n + 7) / 8;

    // Layer 1
    gemm_tiled<128><<<gg, 256>>>(h, W1,  ft,  n);
    gemm_tiled<128><<<gg, 256>>>(h, Wr1, res, n);
    elr_kernel<<<gw, 256>>>(ft, al1, ar1, el, er, n);
    agg_kernel<0><<<gw, 256>>>(off, esrc, el, er, ft, res, x, n);
    // Layer 2 (identity residual)
    gemm_tiled<256><<<gg, 256>>>(x, W2, ft, n);
    elr_kernel<<<gw, 256>>>(ft, al2, ar2, el, er, n);
    agg_kernel<0><<<gw, 256>>>(off, esrc, el, er, ft, x, x, n);
    // Layer 3 (identity residual, no activation, head-mean -> hf)
    gemm_tiled<256><<<gg, 256>>>(x, W3, ft, n);
    elr_kernel<<<gw, 256>>>(ft, al3, ar3, el, er, n);
    agg_kernel<1><<<gw, 256>>>(off, esrc, el, er, ft, x, hfp, n);

    // Edge MLP -> scores (GEMM-tiled, 64 edges per block)
    mlp_kernel<<<(e + 63) / 64, 256>>>(hfp, src, dst, Wm1, bm1, Wm2, bm2, out, e);
}